// round 2
// baseline (speedup 1.0000x reference)
#include <cuda_runtime.h>
#include <cstdint>

// VectorQuantizer, register-tiled SIMT version.
// z_e [32, 64, 32, 32] f32 (layout [b][c][n], n=h*32+w), emb [1024, 64] f32.
// Output: quantized (2097152 f32, layout [b][c][n]) then indices (32768, as f32).
//
// Exact reference numerics (validated rel_err==0.0 in R1 -- DO NOT CHANGE):
//   acc  = sequential fmaf over c ascending (z_c * e_c)
//   A    = sequential fmaf over c ascending (z_c^2)
//   es_k = sequential fmaf over c ascending (e_c^2)
//   t1   = A + es_k          (separate FADD)
//   d    = fmaf(-2, acc, t1)
//   argmin: first-index on ties (strict '<' ascending k; cross-lane merge by
//           lexicographic (d, k)).

#define CTA    256
#define RPC    128      // rows per CTA
#define TK     64       // codes per pass
#define NPASS  16       // 1024 / 64
#define CDIM   64
#define EPAD   68       // padded e-tile row (floats) -> conflict-free STS
#define KCODES 1024
#define N_ROWS 32768

// dynamic smem layout (bytes):
//   zsh   [64][128] f32            0     .. 32768
//   esh   [64][68]  f32            32768 .. 50176
//   es_all[1024]    f32            50176 .. 54272
//   A_sh  [128]     f32            54272 .. 54784
//   kmin  [128]     i32            54784 .. 55296
#define SMEM_BYTES 55296

__global__ __launch_bounds__(CTA, 2)
void vq_tiled_kernel(const float* __restrict__ z,
                     const float* __restrict__ emb,
                     float* __restrict__ out,
                     int out_size)
{
    extern __shared__ char smem[];
    float* zsh    = (float*)(smem);                 // [c][row] : zsh[c*128 + r]
    float* esh    = (float*)(smem + 32768);         // [c][k]   : esh[c*EPAD + k]
    float* es_all = (float*)(smem + 50176);
    float* A_sh   = (float*)(smem + 54272);
    int*   kmin_s = (int*)  (smem + 54784);

    const int tid = threadIdx.x;
    const int bid = blockIdx.x;
    const int b   = bid >> 3;            // batch
    const int n0  = (bid & 7) * RPC;     // first n of this CTA's 128 rows

    const float4* embv = (const float4*)emb;

    // ---- stage z tile: gmem [c][n0..n0+127] -> zsh[c][row], fully coalesced ----
    {
        const float4* zv = (const float4*)z + (size_t)b * 16384 + (n0 >> 2);
#pragma unroll
        for (int i = 0; i < 8; ++i) {
            int fi = tid + CTA * i;          // 0..2047
            int c  = fi >> 5;                // 32 float4 per c-row
            int nf = fi & 31;
            float4 v = zv[c * 256 + nf];
            *(float4*)&zsh[c * RPC + nf * 4] = v;
        }
    }

    // ---- stage e tile 0 (transposed, padded) ----
    const int k_loc = tid & 63;
    const int c4b   = tid >> 6;          // 0..3
    {
#pragma unroll
        for (int i = 0; i < 4; ++i) {
            int c4 = c4b + 4 * i;
            float4 v = embv[(size_t)k_loc * 16 + c4];
            esh[(c4 * 4 + 0) * EPAD + k_loc] = v.x;
            esh[(c4 * 4 + 1) * EPAD + k_loc] = v.y;
            esh[(c4 * 4 + 2) * EPAD + k_loc] = v.z;
            esh[(c4 * 4 + 3) * EPAD + k_loc] = v.w;
        }
    }

    // ---- es_all: ||e_k||^2 for all 1024 codes (ascending-c sequential) ----
#pragma unroll
    for (int q = 0; q < 4; ++q) {
        int k = tid + CTA * q;
        float s = 0.0f;
#pragma unroll
        for (int i = 0; i < 16; ++i) {
            float4 v = embv[(size_t)k * 16 + i];
            s = fmaf(v.x, v.x, s);
            s = fmaf(v.y, v.y, s);
            s = fmaf(v.z, v.z, s);
            s = fmaf(v.w, v.w, s);
        }
        es_all[k] = s;
    }
    __syncthreads();

    // ---- A[row] = ||z_row||^2 (ascending-c sequential) ----
    if (tid < RPC) {
        float s = 0.0f;
#pragma unroll
        for (int c = 0; c < CDIM; ++c) {
            float v = zsh[c * RPC + tid];
            s = fmaf(v, v, s);
        }
        A_sh[tid] = s;
    }
    __syncthreads();

    // ---- main: 16 passes of 64 codes; thread tile = 4 rows x 8 codes ----
    const int rb = (tid >> 3) * 4;       // row base (0..124)
    const int sb = (tid & 7) * 8;        // code base within tile (0..56)

    float a_reg[4];
#pragma unroll
    for (int r = 0; r < 4; ++r) a_reg[r] = A_sh[rb + r];

    float dmin[4];
    int   kmin[4];
#pragma unroll
    for (int r = 0; r < 4; ++r) { dmin[r] = __int_as_float(0x7f800000); kmin[r] = 0; }

    for (int p = 0; p < NPASS; ++p) {
        // prefetch next tile into registers (latency overlapped with compute)
        float4 ereg[4];
        if (p + 1 < NPASS) {
#pragma unroll
            for (int i = 0; i < 4; ++i)
                ereg[i] = embv[(size_t)((p + 1) * TK + k_loc) * 16 + (c4b + 4 * i)];
        }

        float acc[4][8];
#pragma unroll
        for (int r = 0; r < 4; ++r)
#pragma unroll
            for (int j = 0; j < 8; ++j) acc[r][j] = 0.0f;

#pragma unroll 4
        for (int c = 0; c < CDIM; ++c) {
            float4 zz = *(const float4*)&zsh[c * RPC + rb];
            float4 e0 = *(const float4*)&esh[c * EPAD + sb];
            float4 e1 = *(const float4*)&esh[c * EPAD + sb + 4];
            float zr[4] = {zz.x, zz.y, zz.z, zz.w};
            float ej[8] = {e0.x, e0.y, e0.z, e0.w, e1.x, e1.y, e1.z, e1.w};
#pragma unroll
            for (int r = 0; r < 4; ++r)
#pragma unroll
                for (int j = 0; j < 8; ++j)
                    acc[r][j] = fmaf(zr[r], ej[j], acc[r][j]);
        }

        // distances + running argmin (ascending k within thread)
        const int kb = p * TK + sb;
#pragma unroll
        for (int r = 0; r < 4; ++r) {
#pragma unroll
            for (int j = 0; j < 8; ++j) {
                float t1 = a_reg[r] + es_all[kb + j];     // FADD (exact ref order)
                float v  = fmaf(-2.0f, acc[r][j], t1);
                if (v < dmin[r]) { dmin[r] = v; kmin[r] = kb + j; }
            }
        }

        // stage next tile into the (single) smem buffer
        if (p + 1 < NPASS) {
            __syncthreads();     // everyone done reading current tile
#pragma unroll
            for (int i = 0; i < 4; ++i) {
                int c4 = c4b + 4 * i;
                esh[(c4 * 4 + 0) * EPAD + k_loc] = ereg[i].x;
                esh[(c4 * 4 + 1) * EPAD + k_loc] = ereg[i].y;
                esh[(c4 * 4 + 2) * EPAD + k_loc] = ereg[i].z;
                esh[(c4 * 4 + 3) * EPAD + k_loc] = ereg[i].w;
            }
            __syncthreads();     // next tile visible
        }
    }

    // ---- merge argmin across the 8 code-lanes of each row group ----
    // code-lanes for a row group are contiguous lanes (l&~7 .. |7) within a warp.
#pragma unroll
    for (int r = 0; r < 4; ++r) {
        float d = dmin[r];
        int   k = kmin[r];
#pragma unroll
        for (int off = 1; off < 8; off <<= 1) {
            float od = __shfl_xor_sync(0xffffffffu, d, off);
            int   ok = __shfl_xor_sync(0xffffffffu, k, off);
            if (od < d || (od == d && ok < k)) { d = od; k = ok; }
        }
        if ((tid & 7) == 0) kmin_s[rb + r] = k;
    }
    __syncthreads();

    // ---- output: quantized (coalesced STG over n) + indices ----
    const size_t obase = (size_t)b * 65536 + n0;
#pragma unroll
    for (int i = 0; i < 32; ++i) {
        int idx = tid + CTA * i;     // 0..8191
        int c   = idx >> 7;
        int row = idx & 127;
        out[obase + (size_t)c * 1024 + row] = __ldg(&emb[kmin_s[row] * CDIM + c]);
    }

    const int idx_base = N_ROWS * CDIM;          // 2097152
    if (tid < RPC) {
        int grow = bid * RPC + tid;
        if (idx_base + grow < out_size)
            out[idx_base + grow] = (float)kmin_s[tid];
    }
}

extern "C" void kernel_launch(void* const* d_in, const int* in_sizes, int n_in,
                              void* d_out, int out_size)
{
    const float* z_e = (const float*)d_in[0];
    const float* emb = (const float*)d_in[1];
    float* out = (float*)d_out;

    static int attr_set = 0;
    if (!attr_set) {
        cudaFuncSetAttribute(vq_tiled_kernel,
                             cudaFuncAttributeMaxDynamicSharedMemorySize, SMEM_BYTES);
        attr_set = 1;
    }
    vq_tiled_kernel<<<N_ROWS / RPC, CTA, SMEM_BYTES>>>(z_e, emb, out, out_size);
}